// round 14
// baseline (speedup 1.0000x reference)
#include <cuda_runtime.h>
#include <cuda_bf16.h>
#include <stdint.h>

#define BATCH   8
#define SEQ     2048
#define EMBED   1024
#define HEAD    128
#define MROWS   16384
#define TQ      16

// Scratch — __device__ globals, no alloc.
__device__ float g_pO[2 * MROWS * HEAD];
__device__ float g_pm[2 * MROWS];
__device__ float g_pl[2 * MROWS];
// K/V projections stored bf16-split (written by proj epilogue)
__device__ __align__(16) __nv_bfloat16 g_Khi[MROWS * HEAD];
__device__ __align__(16) __nv_bfloat16 g_Klo[MROWS * HEAD];
__device__ __align__(16) __nv_bfloat16 g_Vhi[MROWS * HEAD];
__device__ __align__(16) __nv_bfloat16 g_Vlo[MROWS * HEAD];
// W transposed + bf16-split for proj
__device__ __align__(16) __nv_bfloat16 g_wt_hi[2 * HEAD * EMBED];
__device__ __align__(16) __nv_bfloat16 g_wt_lo[2 * HEAD * EMBED];

// ---------------------------------------------------------------------------
__device__ __forceinline__ uint32_t smem_u32(const void* p) {
    uint32_t a;
    asm("{ .reg .u64 t; cvta.to.shared.u64 t, %1; cvt.u32.u64 %0, t; }"
        : "=r"(a) : "l"(p));
    return a;
}
__device__ __forceinline__ void ldsm_x4(uint32_t* r, uint32_t addr) {
    asm volatile("ldmatrix.sync.aligned.m8n8.x4.shared.b16 {%0,%1,%2,%3}, [%4];"
                 : "=r"(r[0]), "=r"(r[1]), "=r"(r[2]), "=r"(r[3]) : "r"(addr));
}
__device__ __forceinline__ void ldsm_x2(uint32_t* r, uint32_t addr) {
    asm volatile("ldmatrix.sync.aligned.m8n8.x2.shared.b16 {%0,%1}, [%2];"
                 : "=r"(r[0]), "=r"(r[1]) : "r"(addr));
}
__device__ __forceinline__ void ldsm_x2t(uint32_t* r, uint32_t addr) {
    asm volatile("ldmatrix.sync.aligned.m8n8.x2.trans.shared.b16 {%0,%1}, [%2];"
                 : "=r"(r[0]), "=r"(r[1]) : "r"(addr));
}
__device__ __forceinline__ void mma_bf16(float* c, const uint32_t* a, const uint32_t* b) {
    asm volatile(
        "mma.sync.aligned.m16n8k16.row.col.f32.bf16.bf16.f32 "
        "{%0,%1,%2,%3}, {%4,%5,%6,%7}, {%8,%9}, {%0,%1,%2,%3};"
        : "+f"(c[0]), "+f"(c[1]), "+f"(c[2]), "+f"(c[3])
        : "r"(a[0]), "r"(a[1]), "r"(a[2]), "r"(a[3]), "r"(b[0]), "r"(b[1]));
}
__device__ __forceinline__ void split2(float a, float b, uint32_t& hi, uint32_t& lo) {
    __nv_bfloat162 h = __floats2bfloat162_rn(a, b);
    float2 hf = __bfloat1622float2(h);
    __nv_bfloat162 l = __floats2bfloat162_rn(a - hf.x, b - hf.y);
    hi = *(uint32_t*)&h;
    lo = *(uint32_t*)&l;
}
__device__ __forceinline__ void cpa16(uint32_t s, const void* g) {
    asm volatile("cp.async.cg.shared.global [%0], [%1], 16;" :: "r"(s), "l"(g));
}
__device__ __forceinline__ void cpa_commit() {
    asm volatile("cp.async.commit_group;" ::: "memory");
}
template <int N>
__device__ __forceinline__ void cpa_wait() {
    asm volatile("cp.async.wait_group %0;" :: "n"(N) : "memory");
}

// ---------------------------------------------------------------------------
// W prep: transpose + bf16-split. Wk/Wv are [1024][128].
// ---------------------------------------------------------------------------
__global__ __launch_bounds__(256) void wprep_kernel(
    const float* __restrict__ Wk, const float* __restrict__ Wv)
{
    int idx = blockIdx.x * 256 + threadIdx.x;
    int n = idx & 127;
    int k = (idx >> 7) & 1023;
    int m = idx >> 17;
    float f = (m ? Wv : Wk)[k * HEAD + n];
    __nv_bfloat16 hi = __float2bfloat16(f);
    float rem = f - __bfloat162float(hi);
    __nv_bfloat16 lo = __float2bfloat16(rem);
    size_t o = (size_t)(m * HEAD + n) * EMBED + k;
    g_wt_hi[o] = hi;
    g_wt_lo[o] = lo;
}

// ---------------------------------------------------------------------------
// Projection GEMM via mma.sync bf16 (3-product split), PIPELINED:
// B double-buffered through cp.async; A register-preloaded.
// ---------------------------------------------------------------------------
#define PSTR 72
#define ATB  18432                    // one tile (128 x PSTR bf16)
#define PROJ_SMEM (6 * ATB)           // Ahi,Alo + B double buffer = 110592

__global__ __launch_bounds__(256) void proj_mma_kernel(const float* __restrict__ x)
{
    extern __shared__ char smem[];
    __nv_bfloat16* Ahi = (__nv_bfloat16*)smem;
    __nv_bfloat16* Alo = (__nv_bfloat16*)(smem + ATB);
    const uint32_t sAhi = smem_u32(Ahi);
    const uint32_t sAlo = sAhi + ATB;
    const uint32_t sB   = sAhi + 2 * ATB;   // buf p: hi = sB + p*2*ATB, lo = +ATB

    const int bm  = blockIdx.x;
    const int bn  = blockIdx.y;
    const int tid = threadIdx.x;
    const int wid = tid >> 5;
    const int lane = tid & 31;

    const int warp_m = (wid >> 2) * 64;
    const int warp_n = (wid & 3) * 32;

    const int r = tid >> 1;
    const int h = tid & 1;
    const float* xrow = x + (size_t)(bm * 128 + r) * EMBED;
    const __nv_bfloat16* wh = g_wt_hi + (size_t)(bn * 128 + r) * EMBED;
    const __nv_bfloat16* wl = g_wt_lo + (size_t)(bn * 128 + r) * EMBED;

    const int lg = lane >> 3, lr = lane & 7;
    const int a_row_off = lr + (lg & 1) * 8;
    const int a_col_off = (lg >> 1) * 8;
    const int b_lane = lane & 15;
    const int b_row_off = b_lane & 7;
    const int b_col_off = (b_lane >> 3) * 8;

    const uint32_t bdst = (uint32_t)(r * PSTR + h * 32) * 2;

    // prologue: B(0) async, A(0) regs -> smem
    {
        uint32_t dh = sB + bdst;
        #pragma unroll
        for (int i = 0; i < 4; i++) {
            cpa16(dh + i * 16,       wh + h * 32 + i * 8);
            cpa16(dh + ATB + i * 16, wl + h * 32 + i * 8);
        }
        cpa_commit();
    }
    float4 fa[8];
    #pragma unroll
    for (int j = 0; j < 8; j++) fa[j] = *(const float4*)&xrow[h * 32 + j * 4];
    #pragma unroll
    for (int j = 0; j < 8; j++) {
        uint2 hi2, lo2;
        split2(fa[j].x, fa[j].y, hi2.x, lo2.x);
        split2(fa[j].z, fa[j].w, hi2.y, lo2.y);
        int off = r * PSTR + h * 32 + j * 4;
        *(uint2*)&Ahi[off] = hi2;
        *(uint2*)&Alo[off] = lo2;
    }

    float acc[4][4][4] = {};

    for (int c = 0; c < 16; c++) {
        if (c < 15) {
            // issue B(c+1) into the other buffer; preload A(c+1) into regs
            uint32_t dh = sB + ((c + 1) & 1) * 2 * ATB + bdst;
            #pragma unroll
            for (int i = 0; i < 4; i++) {
                cpa16(dh + i * 16,       wh + (c + 1) * 64 + h * 32 + i * 8);
                cpa16(dh + ATB + i * 16, wl + (c + 1) * 64 + h * 32 + i * 8);
            }
            cpa_commit();
            #pragma unroll
            for (int j = 0; j < 8; j++)
                fa[j] = *(const float4*)&xrow[(c + 1) * 64 + h * 32 + j * 4];
            cpa_wait<1>();
        } else {
            cpa_wait<0>();
        }
        __syncthreads();   // B(c) + A(c) visible

        const uint32_t sBhi = sB + (c & 1) * 2 * ATB;
        const uint32_t sBlo = sBhi + ATB;

        #pragma unroll
        for (int kk4 = 0; kk4 < 4; kk4++) {
            const int kk = kk4 * 16;
            uint32_t ah[4][4], al[4][4], bh[4][2], bl[4][2];
            #pragma unroll
            for (int mf = 0; mf < 4; mf++) {
                uint32_t eo = (uint32_t)((warp_m + mf * 16 + a_row_off) * PSTR
                                         + kk + a_col_off) * 2;
                ldsm_x4(ah[mf], sAhi + eo);
                ldsm_x4(al[mf], sAlo + eo);
            }
            #pragma unroll
            for (int nf = 0; nf < 4; nf++) {
                uint32_t eo = (uint32_t)((warp_n + nf * 8 + b_row_off) * PSTR
                                         + kk + b_col_off) * 2;
                ldsm_x2(bh[nf], sBhi + eo);
                ldsm_x2(bl[nf], sBlo + eo);
            }
            #pragma unroll
            for (int mf = 0; mf < 4; mf++)
                #pragma unroll
                for (int nf = 0; nf < 4; nf++) {
                    mma_bf16(acc[mf][nf], ah[mf], bh[nf]);
                    mma_bf16(acc[mf][nf], ah[mf], bl[nf]);
                    mma_bf16(acc[mf][nf], al[mf], bh[nf]);
                }
        }

        if (c < 15) {
            __syncthreads();   // all warps done reading A
            #pragma unroll
            for (int j = 0; j < 8; j++) {
                uint2 hi2, lo2;
                split2(fa[j].x, fa[j].y, hi2.x, lo2.x);
                split2(fa[j].z, fa[j].w, hi2.y, lo2.y);
                int off = r * PSTR + h * 32 + j * 4;
                *(uint2*)&Ahi[off] = hi2;
                *(uint2*)&Alo[off] = lo2;
            }
        }
    }

    // epilogue: write bf16 hi/lo split
    __nv_bfloat16* dhi = (bn ? g_Vhi : g_Khi) + (size_t)bm * 128 * HEAD;
    __nv_bfloat16* dlo = (bn ? g_Vlo : g_Klo) + (size_t)bm * 128 * HEAD;
    const int frow = lane >> 2;
    const int fcol = (lane & 3) * 2;
    #pragma unroll
    for (int mf = 0; mf < 4; mf++) {
        #pragma unroll
        for (int nf = 0; nf < 4; nf++) {
            int row0 = warp_m + mf * 16 + frow;
            int col  = warp_n + nf * 8 + fcol;
            uint32_t h0, l0, h1, l1;
            split2(acc[mf][nf][0], acc[mf][nf][1], h0, l0);
            split2(acc[mf][nf][2], acc[mf][nf][3], h1, l1);
            *(uint32_t*)&dhi[(size_t)row0 * HEAD + col]       = h0;
            *(uint32_t*)&dlo[(size_t)row0 * HEAD + col]       = l0;
            *(uint32_t*)&dhi[(size_t)(row0 + 8) * HEAD + col] = h1;
            *(uint32_t*)&dlo[(size_t)(row0 + 8) * HEAD + col] = l1;
        }
    }
}

// ---------------------------------------------------------------------------
// Flash-attention partial, PIPELINED: Q fragments in registers, K double-
// buffered via cp.async (hidden under S+softmax), V via cp.async (hidden
// under S). Numerics identical to the R9 kernel.
// ---------------------------------------------------------------------------
#define KSTR  136
#define KTILE 34816                  // 128 * KSTR * 2 bytes
#define ATTN_SMEM (6 * KTILE)        // K buf x2 (hi+lo) + V (hi+lo) = 208896

__global__ __launch_bounds__(256) void attn_partial(void)
{
    const int t    = blockIdx.x;
    const int qi   = (TQ - 1) - (t >> 4);
    const int b    = (t >> 1) & 7;
    const int half = t & 1;
    const int hm   = (qi + 1) >> 1;
    const int jbeg = half ? hm : 0;
    const int jend = half ? (qi + 1) : hm;

    const int tid  = threadIdx.x;
    const int wid  = tid >> 5;
    const int lane = tid & 31;

    const size_t prow0 = (size_t)half * MROWS + (size_t)b * SEQ + qi * 128;
    const size_t pbase = prow0 * HEAD;

    if (jbeg == jend) {
        float4 z = make_float4(0.f, 0.f, 0.f, 0.f);
        #pragma unroll
        for (int i = 0; i < 16; i++)
            *(float4*)&g_pO[pbase + (size_t)(wid * 16 + i) * HEAD + lane * 4] = z;
        if (tid < 128) { g_pm[prow0 + tid] = -1e30f; g_pl[prow0 + tid] = 0.0f; }
        return;
    }

    extern __shared__ char smc[];
    const uint32_t sK   = smem_u32(smc);            // Kbuf p: hi sK+p*2*KTILE, lo +KTILE
    const uint32_t sVhi = sK + 4 * KTILE;
    const uint32_t sVlo = sVhi + KTILE;
    __nv_bfloat16* Vhi = (__nv_bfloat16*)(smc + 4 * KTILE);
    __nv_bfloat16* Vlo = (__nv_bfloat16*)(smc + 5 * KTILE);

    const int cr = tid >> 1;
    const int ch = tid & 1;
    const size_t batch0 = (size_t)b * SEQ;
    const uint32_t kvdst = (uint32_t)(cr * KSTR + ch * 64) * 2;

    const int lg = lane >> 3, lr = lane & 7;
    const int a_row_off = lr + (lg & 1) * 8;
    const int a_col_off = (lg >> 1) * 8;
    const int b_lane = lane & 15;
    const int b_row_off = b_lane & 7;
    const int b_col_off = (b_lane >> 3) * 8;

    const int warp_m = wid * 16;
    const int frow = lane >> 2;
    const int fc2  = (lane & 3) * 2;

    // --- stage Q (q = key(x)) through the V buffer, hoist fragments to regs ---
    {
        const __nv_bfloat16* qh = g_Khi + (batch0 + qi * 128 + cr) * HEAD + ch * 64;
        const __nv_bfloat16* ql = g_Klo + (batch0 + qi * 128 + cr) * HEAD + ch * 64;
        #pragma unroll
        for (int i = 0; i < 8; i++) {
            *(uint4*)&Vhi[cr * KSTR + ch * 64 + i * 8] = *(const uint4*)&qh[i * 8];
            *(uint4*)&Vlo[cr * KSTR + ch * 64 + i * 8] = *(const uint4*)&ql[i * 8];
        }
    }
    __syncthreads();
    uint32_t qfh[8][4], qfl[8][4];
    #pragma unroll
    for (int ks = 0; ks < 8; ks++) {
        uint32_t ao = (uint32_t)((warp_m + a_row_off) * KSTR + ks * 16 + a_col_off) * 2;
        ldsm_x4(qfh[ks], sVhi + ao);
        ldsm_x4(qfl[ks], sVlo + ao);
    }
    __syncthreads();   // all q-frags read before V is overwritten

    // --- issue K(jbeg) ---
    {
        uint32_t dh = sK + (jbeg & 1) * 2 * KTILE + kvdst;
        const __nv_bfloat16* gh = g_Khi + (batch0 + jbeg * 128 + cr) * HEAD + ch * 64;
        const __nv_bfloat16* gl = g_Klo + (batch0 + jbeg * 128 + cr) * HEAD + ch * 64;
        #pragma unroll
        for (int i = 0; i < 8; i++) {
            cpa16(dh + i * 16,         gh + i * 8);
            cpa16(dh + KTILE + i * 16, gl + i * 8);
        }
        cpa_commit();
    }

    float o[16][4] = {};
    float m0 = -1e30f, m1 = -1e30f, l0 = 0.f, l1 = 0.f;
    const float sc = 0.08838834764831845f;

    for (int j = jbeg; j < jend; j++) {
        // --- issue group G_j = { V(j), K(j+1) } ---
        {
            const __nv_bfloat16* gvh = g_Vhi + (batch0 + j * 128 + cr) * HEAD + ch * 64;
            const __nv_bfloat16* gvl = g_Vlo + (batch0 + j * 128 + cr) * HEAD + ch * 64;
            #pragma unroll
            for (int i = 0; i < 8; i++) {
                cpa16(sVhi + kvdst + i * 16, gvh + i * 8);
                cpa16(sVlo + kvdst + i * 16, gvl + i * 8);
            }
            if (j + 1 < jend) {
                uint32_t dh = sK + ((j + 1) & 1) * 2 * KTILE + kvdst;
                const __nv_bfloat16* gh = g_Khi + (batch0 + (j + 1) * 128 + cr) * HEAD + ch * 64;
                const __nv_bfloat16* gl = g_Klo + (batch0 + (j + 1) * 128 + cr) * HEAD + ch * 64;
                #pragma unroll
                for (int i = 0; i < 8; i++) {
                    cpa16(dh + i * 16,         gh + i * 8);
                    cpa16(dh + KTILE + i * 16, gl + i * 8);
                }
            }
            cpa_commit();
        }
        cpa_wait<1>();      // K(j) (previous group) complete
        __syncthreads();

        // --- S = Q K^T (Q from registers) ---
        const uint32_t sKhi = sK + (j & 1) * 2 * KTILE;
        const uint32_t sKlo = sKhi + KTILE;
        float s[16][4];
        #pragma unroll
        for (int nf = 0; nf < 16; nf++)
            #pragma unroll
            for (int c = 0; c < 4; c++) s[nf][c] = 0.f;

        #pragma unroll 1
        for (int ks = 0; ks < 8; ks++) {
            #pragma unroll
            for (int nf = 0; nf < 16; nf++) {
                uint32_t bh[2], bl[2];
                uint32_t bo = (uint32_t)((nf * 8 + b_row_off) * KSTR + ks * 16 + b_col_off) * 2;
                ldsm_x2(bh, sKhi + bo);
                ldsm_x2(bl, sKlo + bo);
                mma_bf16(s[nf], qfh[ks], bh);
                mma_bf16(s[nf], qfh[ks], bl);
                mma_bf16(s[nf], qfl[ks], bh);
            }
        }

        // --- softmax (registers only; identical math to R9) ---
        #pragma unroll
        for (int nf = 0; nf < 16; nf++)
            #pragma unroll
            for (int c = 0; c < 4; c++) s[nf][c] *= sc;

        if (j == qi) {
            #pragma unroll
            for (int nf = 0; nf < 16; nf++) {
                int c0 = nf * 8 + fc2;
                int r0 = warp_m + frow;
                if (c0 > r0)         s[nf][0] = -1e30f;
                if (c0 + 1 > r0)     s[nf][1] = -1e30f;
                if (c0 > r0 + 8)     s[nf][2] = -1e30f;
                if (c0 + 1 > r0 + 8) s[nf][3] = -1e30f;
            }
        }

        float mx0 = -1e30f, mx1 = -1e30f;
        #pragma unroll
        for (int nf = 0; nf < 16; nf++) {
            mx0 = fmaxf(mx0, fmaxf(s[nf][0], s[nf][1]));
            mx1 = fmaxf(mx1, fmaxf(s[nf][2], s[nf][3]));
        }
        mx0 = fmaxf(mx0, __shfl_xor_sync(0xFFFFFFFFu, mx0, 1));
        mx0 = fmaxf(mx0, __shfl_xor_sync(0xFFFFFFFFu, mx0, 2));
        mx1 = fmaxf(mx1, __shfl_xor_sync(0xFFFFFFFFu, mx1, 1));
        mx1 = fmaxf(mx1, __shfl_xor_sync(0xFFFFFFFFu, mx1, 2));

        float mn0 = fmaxf(m0, mx0);
        float mn1 = fmaxf(m1, mx1);
        float e0 = __expf(m0 - mn0);
        float e1 = __expf(m1 - mn1);
        m0 = mn0; m1 = mn1;

        float sum0 = 0.f, sum1 = 0.f;
        #pragma unroll
        for (int nf = 0; nf < 16; nf++) {
            float p0 = __expf(s[nf][0] - mn0);
            float p1 = __expf(s[nf][1] - mn0);
            float p2 = __expf(s[nf][2] - mn1);
            float p3 = __expf(s[nf][3] - mn1);
            sum0 += p0 + p1;
            sum1 += p2 + p3;
            uint32_t h01, l01, h23, l23;
            split2(p0, p1, h01, l01);
            split2(p2, p3, h23, l23);
            // pack P back into s storage: [0]=ph01 [1]=ph23 [2]=pl01 [3]=pl23
            s[nf][0] = __uint_as_float(h01);
            s[nf][1] = __uint_as_float(h23);
            s[nf][2] = __uint_as_float(l01);
            s[nf][3] = __uint_as_float(l23);
        }
        sum0 += __shfl_xor_sync(0xFFFFFFFFu, sum0, 1);
        sum0 += __shfl_xor_sync(0xFFFFFFFFu, sum0, 2);
        sum1 += __shfl_xor_sync(0xFFFFFFFFu, sum1, 1);
        sum1 += __shfl_xor_sync(0xFFFFFFFFu, sum1, 2);
        l0 = l0 * e0 + sum0;
        l1 = l1 * e1 + sum1;

        #pragma unroll
        for (int nf = 0; nf < 16; nf++) {
            o[nf][0] *= e0; o[nf][1] *= e0;
            o[nf][2] *= e1; o[nf][3] *= e1;
        }

        cpa_wait<0>();      // V(j) complete (and K(j+1) at worst)
        __syncthreads();

        // --- O += P V ---
        #pragma unroll
        for (int ks = 0; ks < 8; ks++) {
            uint32_t ah[4] = {__float_as_uint(s[2 * ks][0]), __float_as_uint(s[2 * ks][1]),
                              __float_as_uint(s[2 * ks + 1][0]), __float_as_uint(s[2 * ks + 1][1])};
            uint32_t al[4] = {__float_as_uint(s[2 * ks][2]), __float_as_uint(s[2 * ks][3]),
                              __float_as_uint(s[2 * ks + 1][2]), __float_as_uint(s[2 * ks + 1][3])};
            #pragma unroll
            for (int nf = 0; nf < 16; nf++) {
                uint32_t bh[2], bl[2];
                uint32_t bo = (uint32_t)((ks * 16 + b_lane) * KSTR + nf * 8) * 2;
                ldsm_x2t(bh, sVhi + bo);
                ldsm_x2t(bl, sVlo + bo);
                mma_bf16(o[nf], ah, bh);
                mma_bf16(o[nf], ah, bl);
                mma_bf16(o[nf], al, bh);
            }
        }
        __syncthreads();   // all warps done with V before next iter's V issue
    }

    // --- write partials ---
    const int r0 = warp_m + frow;
    const int r1 = r0 + 8;
    #pragma unroll
    for (int nf = 0; nf < 16; nf++) {
        *(float2*)&g_pO[pbase + (size_t)r0 * HEAD + nf * 8 + fc2] =
            make_float2(o[nf][0], o[nf][1]);
        *(float2*)&g_pO[pbase + (size_t)r1 * HEAD + nf * 8 + fc2] =
            make_float2(o[nf][2], o[nf][3]);
    }
    if ((lane & 3) == 0) {
        g_pm[prow0 + r0] = m0;
        g_pl[prow0 + r0] = l0;
        g_pm[prow0 + r1] = m1;
        g_pl[prow0 + r1] = l1;
    }
}

// ---------------------------------------------------------------------------
__global__ __launch_bounds__(256) void merge_kernel(float* __restrict__ out)
{
    const int idx = blockIdx.x * 256 + threadIdx.x;
    const int row = idx >> 5;
    const int c4  = idx & 31;

    const float m0 = g_pm[row], m1 = g_pm[MROWS + row];
    const float l0 = g_pl[row], l1 = g_pl[MROWS + row];
    const float m  = fmaxf(m0, m1);
    const float a0 = __expf(m0 - m);
    const float a1 = __expf(m1 - m);
    const float inv = 1.0f / (a0 * l0 + a1 * l1);

    float4 o0 = *(const float4*)&g_pO[(size_t)row * HEAD + c4 * 4];
    float4 o1 = *(const float4*)&g_pO[(size_t)(MROWS + row) * HEAD + c4 * 4];
    float4 r;
    r.x = (a0 * o0.x + a1 * o1.x) * inv;
    r.y = (a0 * o0.y + a1 * o1.y) * inv;
    r.z = (a0 * o0.z + a1 * o1.z) * inv;
    r.w = (a0 * o0.w + a1 * o1.w) * inv;
    *(float4*)&out[(size_t)row * HEAD + c4 * 4] = r;
}

// ---------------------------------------------------------------------------
extern "C" void kernel_launch(void* const* d_in, const int* in_sizes, int n_in,
                              void* d_out, int out_size)
{
    const float* x  = (const float*)d_in[0];
    const float* Wk = (const float*)d_in[1];
    // d_in[2] = W_query: unused (reference uses key() for q too)
    const float* Wv = (const float*)d_in[3];
    float* out = (float*)d_out;

    wprep_kernel<<<1024, 256>>>(Wk, Wv);

    cudaFuncSetAttribute(proj_mma_kernel, cudaFuncAttributeMaxDynamicSharedMemorySize,
                         PROJ_SMEM);
    dim3 pgrid(128, 2);
    proj_mma_kernel<<<pgrid, 256, PROJ_SMEM>>>(x);

    cudaFuncSetAttribute(attn_partial, cudaFuncAttributeMaxDynamicSharedMemorySize,
                         ATTN_SMEM);
    attn_partial<<<256, 256, ATTN_SMEM>>>();

    merge_kernel<<<(MROWS * 32) / 256, 256>>>(out);
}